// round 6
// baseline (speedup 1.0000x reference)
#include <cuda_runtime.h>
#include <cuda_bf16.h>

#define DIM  64
#define NVOX (DIM*DIM*DIM)       // 262144
#define NB_LOSS (NVOX/128)       // 2048 blocks for the loss kernel (128 voxels/block)

// Scratch (no device allocation allowed in kernel_launch)
__device__ int   g_parent[2*NVOX];
__device__ int   g_lab2[2*NVOX];    // interleaved: [2i]=vol0 label, [2i+1]=vol1 label
__device__ float g_partial[NB_LOSS];
__device__ unsigned g_count;

// ---------------- global union-find ----------------

__device__ __forceinline__ int uf_find(int x) {
    int p = g_parent[x];
    while (p != x) {
        int gp = g_parent[p];
        if (gp != p) g_parent[x] = gp;   // path halving; benign race
        x = p;
        p = gp;
    }
    return x;
}

__device__ __forceinline__ void uf_unite(int a, int b) {
    a = uf_find(a);
    b = uf_find(b);
    while (a != b) {
        if (a < b) { int t = a; a = b; b = t; }   // link larger index under smaller
        int old = atomicCAS(&g_parent[a], a, b);
        if (old == a) return;
        a = uf_find(old);
        b = uf_find(b);
    }
}

// ---------------- shared-memory union-find ----------------

__device__ __forceinline__ int sfind(int* sp, int x) {
    int p = sp[x];
    while (p != x) {
        int gp = sp[p];
        if (gp != p) sp[x] = gp;
        x = p;
        p = gp;
    }
    return p;
}

__device__ __forceinline__ void sunite(int* sp, int a, int b) {
    a = sfind(sp, a);
    b = sfind(sp, b);
    while (a != b) {
        if (a < b) { int t = a; a = b; b = t; }
        int old = atomicCAS(&sp[a], a, b);
        if (old == a) return;
        a = sfind(sp, old);
        b = sfind(sp, b);
    }
}

// ---------------- kernels ----------------

// One block per 64x8x4 tile. x-runs resolved via ballot (no x unions);
// y/z unions deduped via ballot. 256 blocks, 256 threads, 8 vox/thread.
__global__ void k_local(const float* __restrict__ pred, const float* __restrict__ labf) {
    __shared__ int sp[2048];
    int b   = blockIdx.x;
    if (b == 0 && threadIdx.x == 0) g_count = 0u;
    int vol = b >> 7;
    int t   = b & 127;
    int y0  = (t & 7) << 3;
    int z0  = (t >> 3) << 2;
    const float* src = vol ? labf : pred;
    int volOff = vol * NVOX;
    int lane = threadIdx.x & 31;

    // init: local idx l = lx | ly<<6 | lz<<9. Each warp = 32 consecutive lx
    // (half an x-row). Parent = start of contiguous fg run within half-row.
    #pragma unroll
    for (int k = 0; k < 8; k++) {
        int l  = threadIdx.x + 256 * k;
        int lx = l & 63, ly = (l >> 6) & 7, lz = l >> 9;
        int g  = ((z0 + lz) << 12) | ((y0 + ly) << 6) | lx;
        bool fg = src[g] > 0.0f;
        unsigned m = __ballot_sync(0xffffffffu, fg);
        int v = -1;
        if (fg) {
            unsigned zeros_below = ~m & ((1u << lane) - 1u);
            int startLane = zeros_below ? (32 - __clz(zeros_below)) : 0;
            v = (l & ~63) | (lx & 32) | startLane;
        }
        sp[l] = v;
    }
    __syncthreads();

    // unions: half-row stitch (lx==32), y edges, z edges (deduped).
    #pragma unroll
    for (int k = 0; k < 8; k++) {
        int l  = threadIdx.x + 256 * k;
        int lx = l & 63, ly = (l >> 6) & 7, lz = l >> 9;
        int s  = sp[l];
        bool fg = (s >= 0);
        int sy = (ly < 7) ? sp[l + 64]  : -1;
        int sz = (lz < 3) ? sp[l + 512] : -1;
        unsigned my = __ballot_sync(0xffffffffu, fg && sy >= 0);
        unsigned mz = __ballot_sync(0xffffffffu, fg && sz >= 0);
        if (fg) {
            if (lx == 32 && sp[l - 1] >= 0) sunite(sp, s, sp[l - 1]);
            if (sy >= 0 && !(lane && ((my >> (lane - 1)) & 1u))) sunite(sp, s, sy);
            if (sz >= 0 && !(lane && ((mz >> (lane - 1)) & 1u))) sunite(sp, s, sz);
        }
    }
    __syncthreads();

    // flatten local roots -> global indices
    #pragma unroll
    for (int k = 0; k < 8; k++) {
        int l  = threadIdx.x + 256 * k;
        int lx = l & 63, ly = (l >> 6) & 7, lz = l >> 9;
        int g  = ((z0 + lz) << 12) | ((y0 + ly) << 6) | lx;
        int v;
        if (sp[l] < 0) v = -1;
        else {
            int r  = sfind(sp, l);
            int rx = r & 63, ry = (r >> 6) & 7, rz = r >> 9;
            v = volOff + (((z0 + rz) << 12) | ((y0 + ry) << 6) | rx);
        }
        g_parent[volOff + g] = v;
    }
}

// Cross-tile border unions (180224 candidate edges), ballot-deduped.
__global__ void k_border() {
    int idx = blockIdx.x * blockDim.x + threadIdx.x;   // < 180224
    int vol = (idx >= 90112);
    int r   = idx - vol * 90112;
    int volOff = vol * NVOX;
    int lane = threadIdx.x & 31;
    int i, stride;
    if (r < 28672) {
        int x = r & 63, z = (r >> 6) & 63, ky = r >> 12;
        int y = ky * 8 + 7;
        i = volOff + ((z << 12) | (y << 6) | x);
        stride = 64;
    } else {
        int s = r - 28672;
        int x = s & 63, y = (s >> 6) & 63, kz = s >> 12;
        int z = kz * 4 + 3;
        i = volOff + ((z << 12) | (y << 6) | x);
        stride = 4096;
    }
    bool both = (g_parent[i] >= 0) && (g_parent[i + stride] >= 0);
    unsigned mm = __ballot_sync(0xffffffffu, both);
    // prev-lane edge (x-1) with both endpoints fg subsumes ours (x-runs
    // within rows are already unioned in k_local).
    if (both && !(lane && ((mm >> (lane - 1)) & 1u))) uf_unite(i, i + stride);
}

// Flatten with 8-way ILP: 4 voxels x 2 volumes per thread; writes interleaved labels.
__global__ void k_flatten() {
    int q = blockIdx.x * blockDim.x + threadIdx.x;   // < NVOX/4
    int i = q * 4;
    int4 pa = *reinterpret_cast<const int4*>(&g_parent[i]);
    int4 pb = *reinterpret_cast<const int4*>(&g_parent[NVOX + i]);

    int p[8] = {pa.x, pa.y, pa.z, pa.w, pb.x, pb.y, pb.z, pb.w};
    bool d[8];
    #pragma unroll
    for (int k = 0; k < 8; k++) {
        int self = (k < 4) ? (i + k) : (NVOX + i + k - 4);
        d[k] = (p[k] < 0) || (p[k] == self);
    }
    bool all = d[0] & d[1] & d[2] & d[3] & d[4] & d[5] & d[6] & d[7];
    while (!all) {
        all = true;
        #pragma unroll
        for (int k = 0; k < 8; k++) {
            if (!d[k]) {
                int n = g_parent[p[k]];
                d[k] = (n == p[k]);
                p[k] = n;
            }
            all = all && d[k];
        }
    }

    int4 o0, o1;
    o0.x = (pa.x < 0) ? 0 : (p[0] + 1);
    o0.y = (pb.x < 0) ? 0 : (p[4] + 1);
    o0.z = (pa.y < 0) ? 0 : (p[1] + 1);
    o0.w = (pb.y < 0) ? 0 : (p[5] + 1);
    o1.x = (pa.z < 0) ? 0 : (p[2] + 1);
    o1.y = (pb.z < 0) ? 0 : (p[6] + 1);
    o1.z = (pa.w < 0) ? 0 : (p[3] + 1);
    o1.w = (pb.w < 0) ? 0 : (p[7] + 1);
    *reinterpret_cast<int4*>(&g_lab2[2*i])     = o0;
    *reinterpret_cast<int4*>(&g_lab2[2*i + 4]) = o1;
}

// ---------------- 27-bit window morphology ----------------
// bit p = dz*9 + dy*3 + dx  (dz,dy,dx in 0..2), matching reference seed layout.

__device__ __forceinline__ unsigned xd(unsigned m) {
    const unsigned X0 = 0x1249249u;
    const unsigned X2 = 0x4924924u;
    return m | ((m & ~X2) << 1) | ((m & ~X0) >> 1);
}
__device__ __forceinline__ unsigned yd(unsigned m) {
    const unsigned Y0 = 0x01C0E07u;
    const unsigned Y2 = 0x70381C0u;
    return m | ((m & ~Y2) << 3) | ((m & ~Y0) >> 3);
}
__device__ __forceinline__ unsigned zd(unsigned m) {
    return (m | (m << 9) | (m >> 9)) & 0x7FFFFFFu;
}
__device__ __forceinline__ unsigned dil26(unsigned m) { return zd(yd(xd(m))); }
__device__ __forceinline__ unsigned dil18(unsigned m) {
    unsigned zm = zd(m);
    return xd(yd(m)) | xd(zm) | yd(zm);
}

// Pair-split loss: even lane = vol0, odd lane = vol1 of the SAME voxel.
// grid = 2048 blocks x 256 threads; 128 voxels per block.
__global__ void k_loss(const float* __restrict__ pred, const float* __restrict__ labf,
                       float* __restrict__ out) {
    __shared__ float sdata[256];
    __shared__ bool  isLast;
    int tid = threadIdx.x;
    int v   = tid & 1;
    int j   = blockIdx.x * 128 + (tid >> 1);

    int x = j & 63, y = (j >> 6) & 63, z = j >> 12;

    int c = g_lab2[2*j + v];

    // Build this volume's 27-bit difference mask.
    unsigned m = 0u;
    int bit = 0;
    #pragma unroll
    for (int dz = -1; dz <= 1; dz++) {
        int zz = min(max(z + dz, 0), 63);
        #pragma unroll
        for (int dy = -1; dy <= 1; dy++) {
            int yy = min(max(y + dy, 0), 63);
            int base = (zz << 12) | (yy << 6);
            #pragma unroll
            for (int dx = -1; dx <= 1; dx++) {
                int xx = min(max(x + dx, 0), 63);
                int jj = base | xx;
                if (g_lab2[2*jj + v] != c) m |= (1u << bit);
                bit++;
            }
        }
    }

    const unsigned ALL = 0x7FFFFFFu;
    const unsigned CEN = 1u << 13;
    unsigned a  = c ? m : 0u;                       // 18-conn target
    unsigned bm = c ? ((~m & ALL) & ~CEN) : 0u;     // 26-conn target

    unsigned s0 = a  & (0u - a);
    unsigned s1 = bm & (0u - bm);
    bool changed = true;
    while (__any_sync(0xffffffffu, changed)) {
        unsigned t0 = dil18(s0) & a;  t0 = dil18(t0) & a;
        unsigned t1 = dil26(s1) & bm; t1 = dil26(t1) & bm;
        changed = ((t0 ^ s0) | (t1 ^ s1)) != 0u;
        s0 = t0; s1 = t1;
    }
    bool one0 = (s0 == a)  && (a  != 0u);
    bool one1 = (s1 == bm) && (bm != 0u);
    bool ns   = (c != 0) && !(one0 && one1);

    // combine non-simple flags across the lane pair
    int nsO = __shfl_xor_sync(0xffffffffu, (int)ns, 1);
    float contrib = 0.0f;
    if (v == 0) {
        float p = pred[j];
        float l = labf[j];
        float cost = fmaxf(p, 0.0f) - p * l + __logf(1.0f + __expf(-fabsf(p)));
        float w = (ns || nsO) ? 5.0f : 1.0f;
        contrib = w * cost;
    }

    sdata[tid] = contrib;
    __syncthreads();
    #pragma unroll
    for (int s = 128; s > 0; s >>= 1) {
        if (tid < s) sdata[tid] += sdata[tid + s];
        __syncthreads();
    }
    if (tid == 0) {
        g_partial[blockIdx.x] = sdata[0];
        __threadfence();
        unsigned old = atomicAdd(&g_count, 1u);
        isLast = (old == (unsigned)(gridDim.x - 1));
    }
    __syncthreads();

    if (isLast) {
        float vv = 0.0f;
        for (int q = tid; q < NB_LOSS; q += 256) vv += g_partial[q];
        sdata[tid] = vv;
        __syncthreads();
        #pragma unroll
        for (int s = 128; s > 0; s >>= 1) {
            if (tid < s) sdata[tid] += sdata[tid + s];
            __syncthreads();
        }
        if (tid == 0) out[0] = sdata[0] / (float)NVOX;
    }
}

extern "C" void kernel_launch(void* const* d_in, const int* in_sizes, int n_in,
                              void* d_out, int out_size) {
    (void)in_sizes; (void)n_in; (void)out_size;
    const float* pred = (const float*)d_in[0];
    const float* labf = (const float*)d_in[1];
    float* out = (float*)d_out;

    k_local<<<256, 256>>>(pred, labf);
    k_border<<<180224 / 256, 256>>>();
    k_flatten<<<(NVOX/4) / 256, 256>>>();
    k_loss<<<NB_LOSS, 256>>>(pred, labf, out);
}

// round 7
// speedup vs baseline: 1.2109x; 1.2109x over previous
#include <cuda_runtime.h>
#include <cuda_bf16.h>

#define DIM  64
#define NVOX (DIM*DIM*DIM)       // 262144
#define NB_LOSS (NVOX/256)       // 1024 blocks for the loss kernel

// Scratch (no device allocation allowed in kernel_launch)
__device__ int   g_parent[2*NVOX];
__device__ int   g_lab2[2*NVOX];    // interleaved: [2i]=vol0 label, [2i+1]=vol1 label
__device__ float g_partial[NB_LOSS];
__device__ unsigned g_count;

// ---------------- global union-find ----------------

__device__ __forceinline__ int uf_find(int x) {
    int p = g_parent[x];
    while (p != x) {
        int gp = g_parent[p];
        if (gp != p) g_parent[x] = gp;   // path halving; benign race
        x = p;
        p = gp;
    }
    return x;
}

__device__ __forceinline__ void uf_unite(int a, int b) {
    a = uf_find(a);
    b = uf_find(b);
    while (a != b) {
        if (a < b) { int t = a; a = b; b = t; }   // link larger index under smaller
        int old = atomicCAS(&g_parent[a], a, b);
        if (old == a) return;
        a = uf_find(old);
        b = uf_find(b);
    }
}

// ---------------- shared-memory union-find ----------------

__device__ __forceinline__ int sfind(int* sp, int x) {
    int p = sp[x];
    while (p != x) {
        int gp = sp[p];
        if (gp != p) sp[x] = gp;
        x = p;
        p = gp;
    }
    return p;
}

__device__ __forceinline__ void sunite(int* sp, int a, int b) {
    a = sfind(sp, a);
    b = sfind(sp, b);
    while (a != b) {
        if (a < b) { int t = a; a = b; b = t; }
        int old = atomicCAS(&sp[a], a, b);
        if (old == a) return;
        a = sfind(sp, old);
        b = sfind(sp, b);
    }
}

// ---------------- kernels ----------------

// One block per 64x8x4 tile. x-runs resolved via ballot (no x unions);
// y/z unions deduped via ballot. 256 blocks, 512 threads, 4 vox/thread.
__global__ void k_local(const float* __restrict__ pred, const float* __restrict__ labf) {
    __shared__ int sp[2048];
    int b   = blockIdx.x;
    if (b == 0 && threadIdx.x == 0) g_count = 0u;
    int vol = b >> 7;
    int t   = b & 127;
    int y0  = (t & 7) << 3;
    int z0  = (t >> 3) << 2;
    const float* src = vol ? labf : pred;
    int volOff = vol * NVOX;
    int lane = threadIdx.x & 31;

    // init: local idx l = lx | ly<<6 | lz<<9. Each warp = 32 consecutive lx
    // (half an x-row). Parent = start of contiguous fg run within half-row.
    #pragma unroll
    for (int k = 0; k < 4; k++) {
        int l  = threadIdx.x + 512 * k;
        int lx = l & 63;
        int g  = ((z0 + (l >> 9)) << 12) | ((y0 + ((l >> 6) & 7)) << 6) | lx;
        bool fg = src[g] > 0.0f;
        unsigned m = __ballot_sync(0xffffffffu, fg);
        int v = -1;
        if (fg) {
            unsigned zeros_below = ~m & ((1u << lane) - 1u);
            int startLane = zeros_below ? (32 - __clz(zeros_below)) : 0;
            v = (l & ~63) | (lx & 32) | startLane;
        }
        sp[l] = v;
    }
    __syncthreads();

    // unions: half-row stitch (lx==32), y edges, z edges (deduped).
    #pragma unroll
    for (int k = 0; k < 4; k++) {
        int l  = threadIdx.x + 512 * k;
        int lx = l & 63, ly = (l >> 6) & 7, lz = l >> 9;
        int s  = sp[l];
        bool fg = (s >= 0);
        int sy = (ly < 7) ? sp[l + 64]  : -1;
        int sz = (lz < 3) ? sp[l + 512] : -1;
        unsigned my = __ballot_sync(0xffffffffu, fg && sy >= 0);
        unsigned mz = __ballot_sync(0xffffffffu, fg && sz >= 0);
        if (fg) {
            if (lx == 32 && sp[l - 1] >= 0) sunite(sp, s, sp[l - 1]);
            if (sy >= 0 && !(lane && ((my >> (lane - 1)) & 1u))) sunite(sp, s, sy);
            if (sz >= 0 && !(lane && ((mz >> (lane - 1)) & 1u))) sunite(sp, s, sz);
        }
    }
    __syncthreads();

    // flatten local roots -> global indices
    #pragma unroll
    for (int k = 0; k < 4; k++) {
        int l  = threadIdx.x + 512 * k;
        int lx = l & 63, ly = (l >> 6) & 7, lz = l >> 9;
        int g  = ((z0 + lz) << 12) | ((y0 + ly) << 6) | lx;
        int v;
        if (sp[l] < 0) v = -1;
        else {
            int r  = sfind(sp, l);
            int rx = r & 63, ry = (r >> 6) & 7, rz = r >> 9;
            v = volOff + (((z0 + rz) << 12) | ((y0 + ry) << 6) | rx);
        }
        g_parent[volOff + g] = v;
    }
}

// Cross-tile border unions (180224 candidate edges), ballot-deduped.
__global__ void k_border() {
    int idx = blockIdx.x * blockDim.x + threadIdx.x;   // < 180224
    int vol = (idx >= 90112);
    int r   = idx - vol * 90112;
    int volOff = vol * NVOX;
    int lane = threadIdx.x & 31;
    int i, stride;
    if (r < 28672) {
        int x = r & 63, z = (r >> 6) & 63, ky = r >> 12;
        int y = ky * 8 + 7;
        i = volOff + ((z << 12) | (y << 6) | x);
        stride = 64;
    } else {
        int s = r - 28672;
        int x = s & 63, y = (s >> 6) & 63, kz = s >> 12;
        int z = kz * 4 + 3;
        i = volOff + ((z << 12) | (y << 6) | x);
        stride = 4096;
    }
    bool both = (g_parent[i] >= 0) && (g_parent[i + stride] >= 0);
    unsigned mm = __ballot_sync(0xffffffffu, both);
    // prev-lane edge (x-1) with both endpoints fg subsumes ours (x-runs
    // within rows are already unioned in k_local).
    if (both && !(lane && ((mm >> (lane - 1)) & 1u))) uf_unite(i, i + stride);
}

// Flatten with 8-way ILP: 4 voxels x 2 volumes per thread; writes interleaved labels.
__global__ void k_flatten() {
    int q = blockIdx.x * blockDim.x + threadIdx.x;   // < NVOX/4
    int i = q * 4;
    int4 pa = *reinterpret_cast<const int4*>(&g_parent[i]);
    int4 pb = *reinterpret_cast<const int4*>(&g_parent[NVOX + i]);

    int p[8] = {pa.x, pa.y, pa.z, pa.w, pb.x, pb.y, pb.z, pb.w};
    bool d[8];
    #pragma unroll
    for (int k = 0; k < 8; k++) {
        int self = (k < 4) ? (i + k) : (NVOX + i + k - 4);
        d[k] = (p[k] < 0) || (p[k] == self);
    }
    bool all = d[0] & d[1] & d[2] & d[3] & d[4] & d[5] & d[6] & d[7];
    while (!all) {
        all = true;
        #pragma unroll
        for (int k = 0; k < 8; k++) {
            if (!d[k]) {
                int n = g_parent[p[k]];
                d[k] = (n == p[k]);
                p[k] = n;
            }
            all = all && d[k];
        }
    }

    int4 o0, o1;
    o0.x = (pa.x < 0) ? 0 : (p[0] + 1);
    o0.y = (pb.x < 0) ? 0 : (p[4] + 1);
    o0.z = (pa.y < 0) ? 0 : (p[1] + 1);
    o0.w = (pb.y < 0) ? 0 : (p[5] + 1);
    o1.x = (pa.z < 0) ? 0 : (p[2] + 1);
    o1.y = (pb.z < 0) ? 0 : (p[6] + 1);
    o1.z = (pa.w < 0) ? 0 : (p[3] + 1);
    o1.w = (pb.w < 0) ? 0 : (p[7] + 1);
    *reinterpret_cast<int4*>(&g_lab2[2*i])     = o0;
    *reinterpret_cast<int4*>(&g_lab2[2*i + 4]) = o1;
}

// ---------------- 27-bit window morphology ----------------
// bit p = dz*9 + dy*3 + dx  (dz,dy,dx in 0..2), matching reference seed layout.

__device__ __forceinline__ unsigned xd(unsigned m) {
    const unsigned X0 = 0x1249249u;
    const unsigned X2 = 0x4924924u;
    return m | ((m & ~X2) << 1) | ((m & ~X0) >> 1);
}
__device__ __forceinline__ unsigned yd(unsigned m) {
    const unsigned Y0 = 0x01C0E07u;
    const unsigned Y2 = 0x70381C0u;
    return m | ((m & ~Y2) << 3) | ((m & ~Y0) >> 3);
}
__device__ __forceinline__ unsigned zd(unsigned m) {
    return (m | (m << 9) | (m >> 9)) & 0x7FFFFFFu;
}
__device__ __forceinline__ unsigned dil26(unsigned m) { return zd(yd(xd(m))); }
__device__ __forceinline__ unsigned dil18(unsigned m) {
    unsigned zm = zd(m);
    return xd(yd(m)) | xd(zm) | yd(zm);
}

__global__ void k_loss(const float* __restrict__ pred, const float* __restrict__ labf,
                       float* __restrict__ out) {
    __shared__ float sdata[256];
    __shared__ bool  isLast;
    int i = blockIdx.x * 256 + threadIdx.x;

    int x = i & 63, y = (i >> 6) & 63, z = i >> 12;

    int2 cc = *reinterpret_cast<const int2*>(&g_lab2[2*i]);
    int c0 = cc.x, c1 = cc.y;

    // Build 27-bit difference masks for both volumes with shared addressing.
    unsigned m0 = 0u, m1 = 0u;
    int bit = 0;
    #pragma unroll
    for (int dz = -1; dz <= 1; dz++) {
        int zz = min(max(z + dz, 0), 63);
        #pragma unroll
        for (int dy = -1; dy <= 1; dy++) {
            int yy = min(max(y + dy, 0), 63);
            int base = (zz << 12) | (yy << 6);
            #pragma unroll
            for (int dx = -1; dx <= 1; dx++) {
                int xx = min(max(x + dx, 0), 63);
                int j = base | xx;
                int2 lb = *reinterpret_cast<const int2*>(&g_lab2[2*j]);
                if (lb.x != c0) m0 |= (1u << bit);
                if (lb.y != c1) m1 |= (1u << bit);
                bit++;
            }
        }
    }

    const unsigned ALL = 0x7FFFFFFu;
    const unsigned CEN = 1u << 13;
    unsigned a  = c0 ? m0 : 0u;                      // 18-conn target
    unsigned bm = c0 ? ((~m0 & ALL) & ~CEN) : 0u;    // 26-conn target
    unsigned c  = c1 ? m1 : 0u;
    unsigned d  = c1 ? ((~m1 & ALL) & ~CEN) : 0u;

    unsigned s0 = a  & (0u - a);
    unsigned s1 = bm & (0u - bm);
    unsigned s2 = c  & (0u - c);
    unsigned s3 = d  & (0u - d);
    bool changed = true;
    while (__any_sync(0xffffffffu, changed)) {
        unsigned t0 = dil18(s0) & a;
        unsigned t1 = dil26(s1) & bm;
        unsigned t2 = dil18(s2) & c;
        unsigned t3 = dil26(s3) & d;
        changed = ((t0 ^ s0) | (t1 ^ s1) | (t2 ^ s2) | (t3 ^ s3)) != 0u;
        s0 = t0; s1 = t1; s2 = t2; s3 = t3;
    }
    bool one0 = (s0 == a)  && (a  != 0u);
    bool one1 = (s1 == bm) && (bm != 0u);
    bool one2 = (s2 == c)  && (c  != 0u);
    bool one3 = (s3 == d)  && (d  != 0u);
    bool ns0 = (c0 != 0) && !(one0 && one1);
    bool ns1 = (c1 != 0) && !(one2 && one3);

    float p = pred[i];
    float l = labf[i];
    float cost = fmaxf(p, 0.0f) - p * l + __logf(1.0f + __expf(-fabsf(p)));
    float w = (ns0 || ns1) ? 5.0f : 1.0f;

    sdata[threadIdx.x] = w * cost;
    __syncthreads();
    #pragma unroll
    for (int s = 128; s > 0; s >>= 1) {
        if (threadIdx.x < s) sdata[threadIdx.x] += sdata[threadIdx.x + s];
        __syncthreads();
    }
    if (threadIdx.x == 0) {
        g_partial[blockIdx.x] = sdata[0];
        __threadfence();
        unsigned old = atomicAdd(&g_count, 1u);
        isLast = (old == (unsigned)(gridDim.x - 1));
    }
    __syncthreads();

    if (isLast) {
        float v = 0.0f;
        for (int j = threadIdx.x; j < NB_LOSS; j += 256) v += g_partial[j];
        sdata[threadIdx.x] = v;
        __syncthreads();
        #pragma unroll
        for (int s = 128; s > 0; s >>= 1) {
            if (threadIdx.x < s) sdata[threadIdx.x] += sdata[threadIdx.x + s];
            __syncthreads();
        }
        if (threadIdx.x == 0) out[0] = sdata[0] / (float)NVOX;
    }
}

extern "C" void kernel_launch(void* const* d_in, const int* in_sizes, int n_in,
                              void* d_out, int out_size) {
    (void)in_sizes; (void)n_in; (void)out_size;
    const float* pred = (const float*)d_in[0];
    const float* labf = (const float*)d_in[1];
    float* out = (float*)d_out;

    k_local<<<256, 512>>>(pred, labf);
    k_border<<<180224 / 256, 256>>>();
    k_flatten<<<(NVOX/4) / 256, 256>>>();
    k_loss<<<NB_LOSS, 256>>>(pred, labf, out);
}

// round 8
// speedup vs baseline: 1.2731x; 1.0514x over previous
#include <cuda_runtime.h>
#include <cuda_bf16.h>

#define DIM  64
#define NVOX (DIM*DIM*DIM)       // 262144
#define NB_LOSS (NVOX/256)       // 1024 blocks for the loss kernel

// Scratch (no device allocation allowed in kernel_launch)
__device__ int   g_parent[2*NVOX];
__device__ int   g_lab2[2*NVOX];    // interleaved: [2i]=vol0 label, [2i+1]=vol1 label
__device__ float g_partial[NB_LOSS];
__device__ unsigned g_count;

// ---------------- global union-find ----------------

__device__ __forceinline__ int uf_find(int x) {
    int p = g_parent[x];
    while (p != x) {
        int gp = g_parent[p];
        if (gp != p) g_parent[x] = gp;   // path halving; benign race
        x = p;
        p = gp;
    }
    return x;
}

__device__ __forceinline__ void uf_unite(int a, int b) {
    a = uf_find(a);
    b = uf_find(b);
    while (a != b) {
        if (a < b) { int t = a; a = b; b = t; }   // link larger index under smaller
        int old = atomicCAS(&g_parent[a], a, b);
        if (old == a) return;
        a = uf_find(old);
        b = uf_find(b);
    }
}

// ---------------- shared-memory union-find ----------------

__device__ __forceinline__ int sfind(int* sp, int x) {
    int p = sp[x];
    while (p != x) {
        int gp = sp[p];
        if (gp != p) sp[x] = gp;
        x = p;
        p = gp;
    }
    return p;
}

__device__ __forceinline__ void sunite(int* sp, int a, int b) {
    a = sfind(sp, a);
    b = sfind(sp, b);
    while (a != b) {
        if (a < b) { int t = a; a = b; b = t; }
        int old = atomicCAS(&sp[a], a, b);
        if (old == a) return;
        a = sfind(sp, old);
        b = sfind(sp, b);
    }
}

// ---------------- kernels ----------------

// One block per 64x8x4 tile. x-runs resolved via ballot (no x unions);
// y/z unions deduped via ballot. 256 blocks, 512 threads, 4 vox/thread.
__global__ void k_local(const float* __restrict__ pred, const float* __restrict__ labf) {
    __shared__ int sp[2048];
    int b   = blockIdx.x;
    if (b == 0 && threadIdx.x == 0) g_count = 0u;
    int vol = b >> 7;
    int t   = b & 127;
    int y0  = (t & 7) << 3;
    int z0  = (t >> 3) << 2;
    const float* src = vol ? labf : pred;
    int volOff = vol * NVOX;
    int lane = threadIdx.x & 31;

    // init: local idx l = lx | ly<<6 | lz<<9. Each warp = 32 consecutive lx
    // (half an x-row). Parent = start of contiguous fg run within half-row.
    #pragma unroll
    for (int k = 0; k < 4; k++) {
        int l  = threadIdx.x + 512 * k;
        int lx = l & 63;
        int g  = ((z0 + (l >> 9)) << 12) | ((y0 + ((l >> 6) & 7)) << 6) | lx;
        bool fg = src[g] > 0.0f;
        unsigned m = __ballot_sync(0xffffffffu, fg);
        int v = -1;
        if (fg) {
            unsigned zeros_below = ~m & ((1u << lane) - 1u);
            int startLane = zeros_below ? (32 - __clz(zeros_below)) : 0;
            v = (l & ~63) | (lx & 32) | startLane;
        }
        sp[l] = v;
    }
    __syncthreads();

    // unions: half-row stitch (lx==32), y edges, z edges (deduped).
    #pragma unroll
    for (int k = 0; k < 4; k++) {
        int l  = threadIdx.x + 512 * k;
        int lx = l & 63, ly = (l >> 6) & 7, lz = l >> 9;
        int s  = sp[l];
        bool fg = (s >= 0);
        int sy = (ly < 7) ? sp[l + 64]  : -1;
        int sz = (lz < 3) ? sp[l + 512] : -1;
        unsigned my = __ballot_sync(0xffffffffu, fg && sy >= 0);
        unsigned mz = __ballot_sync(0xffffffffu, fg && sz >= 0);
        if (fg) {
            if (lx == 32 && sp[l - 1] >= 0) sunite(sp, s, sp[l - 1]);
            if (sy >= 0 && !(lane && ((my >> (lane - 1)) & 1u))) sunite(sp, s, sy);
            if (sz >= 0 && !(lane && ((mz >> (lane - 1)) & 1u))) sunite(sp, s, sz);
        }
    }
    __syncthreads();

    // flatten local roots -> global indices
    #pragma unroll
    for (int k = 0; k < 4; k++) {
        int l  = threadIdx.x + 512 * k;
        int lx = l & 63, ly = (l >> 6) & 7, lz = l >> 9;
        int g  = ((z0 + lz) << 12) | ((y0 + ly) << 6) | lx;
        int v;
        if (sp[l] < 0) v = -1;
        else {
            int r  = sfind(sp, l);
            int rx = r & 63, ry = (r >> 6) & 7, rz = r >> 9;
            v = volOff + (((z0 + rz) << 12) | ((y0 + ry) << 6) | rx);
        }
        g_parent[volOff + g] = v;
    }
}

// Cross-tile border unions (180224 candidate edges), ballot-deduped.
__global__ void k_border() {
    int idx = blockIdx.x * blockDim.x + threadIdx.x;   // < 180224
    int vol = (idx >= 90112);
    int r   = idx - vol * 90112;
    int volOff = vol * NVOX;
    int lane = threadIdx.x & 31;
    int i, stride;
    if (r < 28672) {
        int x = r & 63, z = (r >> 6) & 63, ky = r >> 12;
        int y = ky * 8 + 7;
        i = volOff + ((z << 12) | (y << 6) | x);
        stride = 64;
    } else {
        int s = r - 28672;
        int x = s & 63, y = (s >> 6) & 63, kz = s >> 12;
        int z = kz * 4 + 3;
        i = volOff + ((z << 12) | (y << 6) | x);
        stride = 4096;
    }
    bool both = (g_parent[i] >= 0) && (g_parent[i + stride] >= 0);
    unsigned mm = __ballot_sync(0xffffffffu, both);
    // prev-lane edge (x-1) with both endpoints fg subsumes ours (x-runs
    // within rows are already unioned in k_local).
    if (both && !(lane && ((mm >> (lane - 1)) & 1u))) uf_unite(i, i + stride);
}

// Flatten with 8-way ILP: 4 voxels x 2 volumes per thread; writes interleaved labels.
__global__ void k_flatten() {
    int q = blockIdx.x * blockDim.x + threadIdx.x;   // < NVOX/4
    int i = q * 4;
    int4 pa = *reinterpret_cast<const int4*>(&g_parent[i]);
    int4 pb = *reinterpret_cast<const int4*>(&g_parent[NVOX + i]);

    int p[8] = {pa.x, pa.y, pa.z, pa.w, pb.x, pb.y, pb.z, pb.w};
    bool d[8];
    #pragma unroll
    for (int k = 0; k < 8; k++) {
        int self = (k < 4) ? (i + k) : (NVOX + i + k - 4);
        d[k] = (p[k] < 0) || (p[k] == self);
    }
    bool all = d[0] & d[1] & d[2] & d[3] & d[4] & d[5] & d[6] & d[7];
    while (!all) {
        all = true;
        #pragma unroll
        for (int k = 0; k < 8; k++) {
            if (!d[k]) {
                int n = g_parent[p[k]];
                d[k] = (n == p[k]);
                p[k] = n;
            }
            all = all && d[k];
        }
    }

    int4 o0, o1;
    o0.x = (pa.x < 0) ? 0 : (p[0] + 1);
    o0.y = (pb.x < 0) ? 0 : (p[4] + 1);
    o0.z = (pa.y < 0) ? 0 : (p[1] + 1);
    o0.w = (pb.y < 0) ? 0 : (p[5] + 1);
    o1.x = (pa.z < 0) ? 0 : (p[2] + 1);
    o1.y = (pb.z < 0) ? 0 : (p[6] + 1);
    o1.z = (pa.w < 0) ? 0 : (p[3] + 1);
    o1.w = (pb.w < 0) ? 0 : (p[7] + 1);
    *reinterpret_cast<int4*>(&g_lab2[2*i])     = o0;
    *reinterpret_cast<int4*>(&g_lab2[2*i + 4]) = o1;
}

// ---------------- 27-bit window morphology ----------------
// bit p = dz*9 + dy*3 + dx  (dz,dy,dx in 0..2), matching reference seed layout.

__device__ __forceinline__ unsigned xd(unsigned m) {
    const unsigned X0 = 0x1249249u;
    const unsigned X2 = 0x4924924u;
    return m | ((m & ~X2) << 1) | ((m & ~X0) >> 1);
}
__device__ __forceinline__ unsigned yd(unsigned m) {
    const unsigned Y0 = 0x01C0E07u;
    const unsigned Y2 = 0x70381C0u;
    return m | ((m & ~Y2) << 3) | ((m & ~Y0) >> 3);
}
__device__ __forceinline__ unsigned zd(unsigned m) {
    return (m | (m << 9) | (m >> 9)) & 0x7FFFFFFu;
}
__device__ __forceinline__ unsigned dil26(unsigned m) { return zd(yd(xd(m))); }
__device__ __forceinline__ unsigned dil18(unsigned m) {
    unsigned zm = zd(m);
    return xd(yd(m)) | xd(zm) | yd(zm);
}

// Pick a low-eccentricity seed: prefer face-adjacent bits (6-neighbors of
// center) — halves typical flood iteration count vs the lowest (corner) bit.
#define FACES 0x415410u
__device__ __forceinline__ unsigned pick_seed(unsigned m) {
    unsigned f = m & FACES;
    unsigned src = f ? f : m;
    return src & (0u - src);
}

__global__ void k_loss(const float* __restrict__ pred, const float* __restrict__ labf,
                       float* __restrict__ out) {
    __shared__ float sdata[256];
    __shared__ bool  isLast;
    int i = blockIdx.x * 256 + threadIdx.x;

    int x = i & 63, y = (i >> 6) & 63, z = i >> 12;

    int2 cc = *reinterpret_cast<const int2*>(&g_lab2[2*i]);
    int c0 = cc.x, c1 = cc.y;

    // Build 27-bit difference masks for both volumes with shared addressing.
    unsigned m0 = 0u, m1 = 0u;
    int bit = 0;
    #pragma unroll
    for (int dz = -1; dz <= 1; dz++) {
        int zz = min(max(z + dz, 0), 63);
        #pragma unroll
        for (int dy = -1; dy <= 1; dy++) {
            int yy = min(max(y + dy, 0), 63);
            int base = (zz << 12) | (yy << 6);
            #pragma unroll
            for (int dx = -1; dx <= 1; dx++) {
                int xx = min(max(x + dx, 0), 63);
                int j = base | xx;
                int2 lb = *reinterpret_cast<const int2*>(&g_lab2[2*j]);
                if (lb.x != c0) m0 |= (1u << bit);
                if (lb.y != c1) m1 |= (1u << bit);
                bit++;
            }
        }
    }

    const unsigned ALL = 0x7FFFFFFu;
    const unsigned CEN = 1u << 13;
    unsigned a  = c0 ? m0 : 0u;                      // 18-conn target
    unsigned bm = c0 ? ((~m0 & ALL) & ~CEN) : 0u;    // 26-conn target
    unsigned c  = c1 ? m1 : 0u;
    unsigned d  = c1 ? ((~m1 & ALL) & ~CEN) : 0u;

    unsigned s0 = pick_seed(a);
    unsigned s1 = pick_seed(bm);
    unsigned s2 = pick_seed(c);
    unsigned s3 = pick_seed(d);
    bool changed = true;
    while (__any_sync(0xffffffffu, changed)) {
        unsigned t0 = dil18(s0) & a;
        unsigned t1 = dil26(s1) & bm;
        unsigned t2 = dil18(s2) & c;
        unsigned t3 = dil26(s3) & d;
        changed = ((t0 ^ s0) | (t1 ^ s1) | (t2 ^ s2) | (t3 ^ s3)) != 0u;
        s0 = t0; s1 = t1; s2 = t2; s3 = t3;
    }
    bool one0 = (s0 == a)  && (a  != 0u);
    bool one1 = (s1 == bm) && (bm != 0u);
    bool one2 = (s2 == c)  && (c  != 0u);
    bool one3 = (s3 == d)  && (d  != 0u);
    bool ns0 = (c0 != 0) && !(one0 && one1);
    bool ns1 = (c1 != 0) && !(one2 && one3);

    float p = pred[i];
    float l = labf[i];
    float cost = fmaxf(p, 0.0f) - p * l + __logf(1.0f + __expf(-fabsf(p)));
    float w = (ns0 || ns1) ? 5.0f : 1.0f;

    sdata[threadIdx.x] = w * cost;
    __syncthreads();
    #pragma unroll
    for (int s = 128; s > 0; s >>= 1) {
        if (threadIdx.x < s) sdata[threadIdx.x] += sdata[threadIdx.x + s];
        __syncthreads();
    }
    if (threadIdx.x == 0) {
        g_partial[blockIdx.x] = sdata[0];
        __threadfence();
        unsigned old = atomicAdd(&g_count, 1u);
        isLast = (old == (unsigned)(gridDim.x - 1));
    }
    __syncthreads();

    if (isLast) {
        float v = 0.0f;
        for (int j = threadIdx.x; j < NB_LOSS; j += 256) v += g_partial[j];
        sdata[threadIdx.x] = v;
        __syncthreads();
        #pragma unroll
        for (int s = 128; s > 0; s >>= 1) {
            if (threadIdx.x < s) sdata[threadIdx.x] += sdata[threadIdx.x + s];
            __syncthreads();
        }
        if (threadIdx.x == 0) out[0] = sdata[0] / (float)NVOX;
    }
}

extern "C" void kernel_launch(void* const* d_in, const int* in_sizes, int n_in,
                              void* d_out, int out_size) {
    (void)in_sizes; (void)n_in; (void)out_size;
    const float* pred = (const float*)d_in[0];
    const float* labf = (const float*)d_in[1];
    float* out = (float*)d_out;

    k_local<<<256, 512>>>(pred, labf);
    k_border<<<180224 / 256, 256>>>();
    k_flatten<<<(NVOX/4) / 256, 256>>>();
    k_loss<<<NB_LOSS, 256>>>(pred, labf, out);
}

// round 9
// speedup vs baseline: 1.2987x; 1.0201x over previous
#include <cuda_runtime.h>
#include <cuda_bf16.h>

#define DIM  64
#define NVOX (DIM*DIM*DIM)       // 262144
#define NB_LOSS (NVOX/256)       // 1024 blocks for the loss kernel

// Scratch (no device allocation allowed in kernel_launch)
__device__ int   g_parent[2*NVOX];
__device__ int   g_lab2[2*NVOX];    // interleaved: [2i]=vol0 label, [2i+1]=vol1 label
__device__ float g_partial[NB_LOSS];
__device__ unsigned g_count;

// ---------------- global union-find ----------------

__device__ __forceinline__ int uf_find(int x) {
    int p = g_parent[x];
    while (p != x) {
        int gp = g_parent[p];
        if (gp != p) g_parent[x] = gp;   // path halving; benign race
        x = p;
        p = gp;
    }
    return x;
}

__device__ __forceinline__ void uf_unite(int a, int b) {
    a = uf_find(a);
    b = uf_find(b);
    while (a != b) {
        if (a < b) { int t = a; a = b; b = t; }   // link larger index under smaller
        int old = atomicCAS(&g_parent[a], a, b);
        if (old == a) return;
        a = uf_find(old);
        b = uf_find(b);
    }
}

// ---------------- shared-memory union-find ----------------

__device__ __forceinline__ int sfind(int* sp, int x) {
    int p = sp[x];
    while (p != x) {
        int gp = sp[p];
        if (gp != p) sp[x] = gp;
        x = p;
        p = gp;
    }
    return p;
}

__device__ __forceinline__ void sunite(int* sp, int a, int b) {
    a = sfind(sp, a);
    b = sfind(sp, b);
    while (a != b) {
        if (a < b) { int t = a; a = b; b = t; }
        int old = atomicCAS(&sp[a], a, b);
        if (old == a) return;
        a = sfind(sp, old);
        b = sfind(sp, b);
    }
}

// ---------------- kernels ----------------

// One block per 64x8x4 tile. x-runs resolved via ballot (no x unions);
// y/z unions deduped via ballot. 256 blocks, 1024 threads, 2 vox/thread.
__global__ void k_local(const float* __restrict__ pred, const float* __restrict__ labf) {
    __shared__ int sp[2048];
    int b   = blockIdx.x;
    if (b == 0 && threadIdx.x == 0) g_count = 0u;
    int vol = b >> 7;
    int t   = b & 127;
    int y0  = (t & 7) << 3;
    int z0  = (t >> 3) << 2;
    const float* src = vol ? labf : pred;
    int volOff = vol * NVOX;
    int lane = threadIdx.x & 31;

    // init: local idx l = lx | ly<<6 | lz<<9. Each warp = 32 consecutive lx
    // (half an x-row). Parent = start of contiguous fg run within half-row.
    #pragma unroll
    for (int k = 0; k < 2; k++) {
        int l  = threadIdx.x + 1024 * k;
        int lx = l & 63;
        int g  = ((z0 + (l >> 9)) << 12) | ((y0 + ((l >> 6) & 7)) << 6) | lx;
        bool fg = src[g] > 0.0f;
        unsigned m = __ballot_sync(0xffffffffu, fg);
        int v = -1;
        if (fg) {
            unsigned zeros_below = ~m & ((1u << lane) - 1u);
            int startLane = zeros_below ? (32 - __clz(zeros_below)) : 0;
            v = (l & ~63) | (lx & 32) | startLane;
        }
        sp[l] = v;
    }
    __syncthreads();

    // unions: half-row stitch (lx==32), y edges, z edges (deduped).
    #pragma unroll
    for (int k = 0; k < 2; k++) {
        int l  = threadIdx.x + 1024 * k;
        int lx = l & 63, ly = (l >> 6) & 7, lz = l >> 9;
        int s  = sp[l];
        bool fg = (s >= 0);
        int sy = (ly < 7) ? sp[l + 64]  : -1;
        int sz = (lz < 3) ? sp[l + 512] : -1;
        unsigned my = __ballot_sync(0xffffffffu, fg && sy >= 0);
        unsigned mz = __ballot_sync(0xffffffffu, fg && sz >= 0);
        if (fg) {
            if (lx == 32 && sp[l - 1] >= 0) sunite(sp, s, sp[l - 1]);
            if (sy >= 0 && !(lane && ((my >> (lane - 1)) & 1u))) sunite(sp, s, sy);
            if (sz >= 0 && !(lane && ((mz >> (lane - 1)) & 1u))) sunite(sp, s, sz);
        }
    }
    __syncthreads();

    // flatten local roots -> global indices
    #pragma unroll
    for (int k = 0; k < 2; k++) {
        int l  = threadIdx.x + 1024 * k;
        int lx = l & 63, ly = (l >> 6) & 7, lz = l >> 9;
        int g  = ((z0 + lz) << 12) | ((y0 + ly) << 6) | lx;
        int v;
        if (sp[l] < 0) v = -1;
        else {
            int r  = sfind(sp, l);
            int rx = r & 63, ry = (r >> 6) & 7, rz = r >> 9;
            v = volOff + (((z0 + rz) << 12) | ((y0 + ry) << 6) | rx);
        }
        g_parent[volOff + g] = v;
    }
}

// Cross-tile border unions (180224 candidate edges), ballot-deduped.
__global__ void k_border() {
    int idx = blockIdx.x * blockDim.x + threadIdx.x;   // < 180224
    int vol = (idx >= 90112);
    int r   = idx - vol * 90112;
    int volOff = vol * NVOX;
    int lane = threadIdx.x & 31;
    int i, stride;
    if (r < 28672) {
        int x = r & 63, z = (r >> 6) & 63, ky = r >> 12;
        int y = ky * 8 + 7;
        i = volOff + ((z << 12) | (y << 6) | x);
        stride = 64;
    } else {
        int s = r - 28672;
        int x = s & 63, y = (s >> 6) & 63, kz = s >> 12;
        int z = kz * 4 + 3;
        i = volOff + ((z << 12) | (y << 6) | x);
        stride = 4096;
    }
    bool both = (g_parent[i] >= 0) && (g_parent[i + stride] >= 0);
    unsigned mm = __ballot_sync(0xffffffffu, both);
    // prev-lane edge (x-1) with both endpoints fg subsumes ours (x-runs
    // within rows are already unioned in k_local).
    if (both && !(lane && ((mm >> (lane - 1)) & 1u))) uf_unite(i, i + stride);
}

// Flatten with 8-way ILP: 4 voxels x 2 volumes per thread; writes interleaved labels.
__global__ void k_flatten() {
    int q = blockIdx.x * blockDim.x + threadIdx.x;   // < NVOX/4
    int i = q * 4;
    int4 pa = *reinterpret_cast<const int4*>(&g_parent[i]);
    int4 pb = *reinterpret_cast<const int4*>(&g_parent[NVOX + i]);

    int p[8] = {pa.x, pa.y, pa.z, pa.w, pb.x, pb.y, pb.z, pb.w};
    bool d[8];
    #pragma unroll
    for (int k = 0; k < 8; k++) {
        int self = (k < 4) ? (i + k) : (NVOX + i + k - 4);
        d[k] = (p[k] < 0) || (p[k] == self);
    }
    bool all = d[0] & d[1] & d[2] & d[3] & d[4] & d[5] & d[6] & d[7];
    while (!all) {
        all = true;
        #pragma unroll
        for (int k = 0; k < 8; k++) {
            if (!d[k]) {
                int n = g_parent[p[k]];
                d[k] = (n == p[k]);
                p[k] = n;
            }
            all = all && d[k];
        }
    }

    int4 o0, o1;
    o0.x = (pa.x < 0) ? 0 : (p[0] + 1);
    o0.y = (pb.x < 0) ? 0 : (p[4] + 1);
    o0.z = (pa.y < 0) ? 0 : (p[1] + 1);
    o0.w = (pb.y < 0) ? 0 : (p[5] + 1);
    o1.x = (pa.z < 0) ? 0 : (p[2] + 1);
    o1.y = (pb.z < 0) ? 0 : (p[6] + 1);
    o1.z = (pa.w < 0) ? 0 : (p[3] + 1);
    o1.w = (pb.w < 0) ? 0 : (p[7] + 1);
    *reinterpret_cast<int4*>(&g_lab2[2*i])     = o0;
    *reinterpret_cast<int4*>(&g_lab2[2*i + 4]) = o1;
}

// ---------------- 27-bit window morphology ----------------
// bit p = dz*9 + dy*3 + dx  (dz,dy,dx in 0..2), matching reference seed layout.

__device__ __forceinline__ unsigned xd(unsigned m) {
    const unsigned X0 = 0x1249249u;
    const unsigned X2 = 0x4924924u;
    return m | ((m & ~X2) << 1) | ((m & ~X0) >> 1);
}
__device__ __forceinline__ unsigned yd(unsigned m) {
    const unsigned Y0 = 0x01C0E07u;
    const unsigned Y2 = 0x70381C0u;
    return m | ((m & ~Y2) << 3) | ((m & ~Y0) >> 3);
}
__device__ __forceinline__ unsigned zd(unsigned m) {
    return (m | (m << 9) | (m >> 9)) & 0x7FFFFFFu;
}
__device__ __forceinline__ unsigned dil26(unsigned m) { return zd(yd(xd(m))); }
__device__ __forceinline__ unsigned dil18(unsigned m) {
    unsigned zm = zd(m);
    return xd(yd(m)) | xd(zm) | yd(zm);
}

// Pick a low-eccentricity seed: prefer face-adjacent bits (6-neighbors of
// center) — halves typical flood iteration count vs the lowest (corner) bit.
#define FACES 0x415410u
__device__ __forceinline__ unsigned pick_seed(unsigned m) {
    unsigned f = m & FACES;
    unsigned src = f ? f : m;
    return src & (0u - src);
}

__global__ void k_loss(const float* __restrict__ pred, const float* __restrict__ labf,
                       float* __restrict__ out) {
    __shared__ float sdata[256];
    __shared__ bool  isLast;
    int i = blockIdx.x * 256 + threadIdx.x;

    int x = i & 63, y = (i >> 6) & 63, z = i >> 12;

    int2 cc = *reinterpret_cast<const int2*>(&g_lab2[2*i]);
    int c0 = cc.x, c1 = cc.y;

    // Build 27-bit difference masks for both volumes with shared addressing.
    unsigned m0 = 0u, m1 = 0u;
    int bit = 0;
    #pragma unroll
    for (int dz = -1; dz <= 1; dz++) {
        int zz = min(max(z + dz, 0), 63);
        #pragma unroll
        for (int dy = -1; dy <= 1; dy++) {
            int yy = min(max(y + dy, 0), 63);
            int base = (zz << 12) | (yy << 6);
            #pragma unroll
            for (int dx = -1; dx <= 1; dx++) {
                int xx = min(max(x + dx, 0), 63);
                int j = base | xx;
                int2 lb = *reinterpret_cast<const int2*>(&g_lab2[2*j]);
                if (lb.x != c0) m0 |= (1u << bit);
                if (lb.y != c1) m1 |= (1u << bit);
                bit++;
            }
        }
    }

    const unsigned ALL = 0x7FFFFFFu;
    const unsigned CEN = 1u << 13;
    unsigned a  = c0 ? m0 : 0u;                      // 18-conn target
    unsigned bm = c0 ? ((~m0 & ALL) & ~CEN) : 0u;    // 26-conn target
    unsigned c  = c1 ? m1 : 0u;
    unsigned d  = c1 ? ((~m1 & ALL) & ~CEN) : 0u;

    unsigned s0 = pick_seed(a);
    unsigned s1 = pick_seed(bm);
    unsigned s2 = pick_seed(c);
    unsigned s3 = pick_seed(d);

    // Peel 3 vote-free iterations (dilation is idempotent at fixpoint, so
    // over-iterating is harmless); most chains converge within these.
    #pragma unroll
    for (int it = 0; it < 3; it++) {
        s0 = dil18(s0) & a;
        s1 = dil26(s1) & bm;
        s2 = dil18(s2) & c;
        s3 = dil26(s3) & d;
    }

    bool changed = true;
    while (__any_sync(0xffffffffu, changed)) {
        unsigned t0 = dil18(s0) & a;
        unsigned t1 = dil26(s1) & bm;
        unsigned t2 = dil18(s2) & c;
        unsigned t3 = dil26(s3) & d;
        changed = ((t0 ^ s0) | (t1 ^ s1) | (t2 ^ s2) | (t3 ^ s3)) != 0u;
        s0 = t0; s1 = t1; s2 = t2; s3 = t3;
    }
    bool one0 = (s0 == a)  && (a  != 0u);
    bool one1 = (s1 == bm) && (bm != 0u);
    bool one2 = (s2 == c)  && (c  != 0u);
    bool one3 = (s3 == d)  && (d  != 0u);
    bool ns0 = (c0 != 0) && !(one0 && one1);
    bool ns1 = (c1 != 0) && !(one2 && one3);

    float p = pred[i];
    float l = labf[i];
    float cost = fmaxf(p, 0.0f) - p * l + __logf(1.0f + __expf(-fabsf(p)));
    float w = (ns0 || ns1) ? 5.0f : 1.0f;

    sdata[threadIdx.x] = w * cost;
    __syncthreads();
    #pragma unroll
    for (int s = 128; s > 0; s >>= 1) {
        if (threadIdx.x < s) sdata[threadIdx.x] += sdata[threadIdx.x + s];
        __syncthreads();
    }
    if (threadIdx.x == 0) {
        g_partial[blockIdx.x] = sdata[0];
        __threadfence();
        unsigned old = atomicAdd(&g_count, 1u);
        isLast = (old == (unsigned)(gridDim.x - 1));
    }
    __syncthreads();

    if (isLast) {
        float v = 0.0f;
        for (int j = threadIdx.x; j < NB_LOSS; j += 256) v += g_partial[j];
        sdata[threadIdx.x] = v;
        __syncthreads();
        #pragma unroll
        for (int s = 128; s > 0; s >>= 1) {
            if (threadIdx.x < s) sdata[threadIdx.x] += sdata[threadIdx.x + s];
            __syncthreads();
        }
        if (threadIdx.x == 0) out[0] = sdata[0] / (float)NVOX;
    }
}

extern "C" void kernel_launch(void* const* d_in, const int* in_sizes, int n_in,
                              void* d_out, int out_size) {
    (void)in_sizes; (void)n_in; (void)out_size;
    const float* pred = (const float*)d_in[0];
    const float* labf = (const float*)d_in[1];
    float* out = (float*)d_out;

    k_local<<<256, 1024>>>(pred, labf);
    k_border<<<180224 / 256, 256>>>();
    k_flatten<<<(NVOX/4) / 256, 256>>>();
    k_loss<<<NB_LOSS, 256>>>(pred, labf, out);
}